// round 14
// baseline (speedup 1.0000x reference)
#include <cuda_runtime.h>
#include <cuda_fp16.h>
#include <math.h>
#include <stdint.h>

using fp16 = __half;

constexpr int NN  = 20000;      // nodes
constexpr int NE  = 320000;     // edges
constexpr int HID = 512;
constexpr int ED  = 64;
constexpr int KC3 = 2*HID;      // 1024

constexpr int BM = 128, BN = 128, BK = 64, PAD = 8, BKP = BK + PAD;

constexpr int ASZ = BM*BKP;             // A tile
constexpr int BSZ = BN*BKP;             // B tile
constexpr int STG = ASZ + BSZ;          // per-stage elements
constexpr int NSTAGE = 3;
constexpr int SMEM_BYTES = NSTAGE*STG*(int)sizeof(fp16);   // 110592

constexpr float WSC  = 32.0f;           // weight pre-scale (power of 2, exact)
constexpr float WINV = 1.0f/32.0f;

// ---------------- device scratch ----------------
__device__ fp16 g_x[NN*HID];
__device__ fp16 g_ea[NE*ED];
__device__ fp16 g_w1a[HID*HID];
__device__ fp16 g_w1b[HID*HID];
__device__ fp16 g_w1c[HID*ED];
__device__ fp16 g_w2t[HID*HID];
__device__ fp16 g_w3t[HID*KC3];
__device__ fp16 g_w4t[HID*HID];
__device__ int   g_ei[2*NE];
__device__ float g_P[NN*HID];
__device__ float g_Q[NN*HID];
__device__ fp16  g_h[(size_t)NE*HID];
__device__ float g_agg[NN*HID];
__device__ fp16  g_agg_h[NN*HID];
__device__ fp16  g_u[NN*HID];
__device__ float g_y[NN*HID];

// ---------------- helpers ----------------
__device__ __forceinline__ float mishf(float x){
    float t   = __expf(fminf(x, 15.f));
    float num = t * (t + 2.f);
    return x * __fdividef(num, num + 2.f);
}
__device__ __forceinline__ unsigned smem_u32(const void* p){
    return (unsigned)__cvta_generic_to_shared(p);
}
__device__ __forceinline__ void ldsm_x4(unsigned &r0, unsigned &r1, unsigned &r2, unsigned &r3, unsigned addr){
    asm volatile("ldmatrix.sync.aligned.m8n8.x4.shared.b16 {%0,%1,%2,%3}, [%4];"
                 : "=r"(r0), "=r"(r1), "=r"(r2), "=r"(r3) : "r"(addr));
}
__device__ __forceinline__ void mma_f16(float* c, unsigned a0, unsigned a1, unsigned a2, unsigned a3,
                                        unsigned b0, unsigned b1){
    asm volatile("mma.sync.aligned.m16n8k16.row.col.f32.f16.f16.f32 "
                 "{%0,%1,%2,%3}, {%4,%5,%6,%7}, {%8,%9}, {%0,%1,%2,%3};"
                 : "+f"(c[0]), "+f"(c[1]), "+f"(c[2]), "+f"(c[3])
                 : "r"(a0), "r"(a1), "r"(a2), "r"(a3), "r"(b0), "r"(b1));
}
// fp16-accumulator MMA, C=0; result promoted immediately to fp32 (one fp16
// rounding per 16-k partial -> ~2.8e-4 RMS added error on the affected GEMM).
__device__ __forceinline__ void mma_f16h(float* c, unsigned a0, unsigned a1, unsigned a2, unsigned a3,
                                         unsigned b0, unsigned b1){
    unsigned d0, d1;
    asm volatile("mma.sync.aligned.m16n8k16.row.col.f16.f16.f16.f16 "
                 "{%0,%1}, {%2,%3,%4,%5}, {%6,%7}, {%8,%9};"
                 : "=r"(d0), "=r"(d1)
                 : "r"(a0), "r"(a1), "r"(a2), "r"(a3), "r"(b0), "r"(b1),
                   "r"(0u), "r"(0u));
    float2 f0 = __half22float2(*reinterpret_cast<__half2*>(&d0));
    float2 f1 = __half22float2(*reinterpret_cast<__half2*>(&d1));
    c[0] += f0.x; c[1] += f0.y; c[2] += f1.x; c[3] += f1.y;
}
__device__ __forceinline__ uint32_t pack2h(fp16 a, fp16 b){
    __half2 p; p.x = a; p.y = b;
    return *(uint32_t*)&p;
}
__device__ __forceinline__ void cp16(uint32_t dst, const void* src){
    asm volatile("cp.async.cg.shared.global [%0], [%1], 16;" :: "r"(dst), "l"(src));
}
#define CP_COMMIT() asm volatile("cp.async.commit_group;" ::: "memory")
#define CP_WAIT1()  asm volatile("cp.async.wait_group 1;" ::: "memory")
#define CP_WAIT0()  asm volatile("cp.async.wait_group 0;" ::: "memory")

// ---------------- prep kernels (fused) ----------------
constexpr int NX   = NN*HID;
constexpr int NW1A = HID*HID;
constexpr int NW1B = HID*HID;
constexpr int NW1C = ED*HID;
constexpr int NW2  = HID*HID;
constexpr int NW3  = KC3*HID;
constexpr int NW4  = HID*HID;
constexpr int SPLIT_ALL_TOT = NX + NW1A + NW1B + NW1C + NW2 + NW3 + NW4;

__global__ void k_split_all(const float* __restrict__ x,
                            const float* __restrict__ W1,
                            const float* __restrict__ W2,
                            const float* __restrict__ W3,
                            const float* __restrict__ W4){
    int i = blockIdx.x * blockDim.x + threadIdx.x;
    if (i >= SPLIT_ALL_TOT) return;
    if (i < NX){
        g_x[i] = __float2half(x[i]);
        return;
    }
    i -= NX;
    const float* src; fp16 *w; int K;
    if      (i < NW1A){                              src = W1;                     w=g_w1a; K=HID; }
    else if ((i -= NW1A) < NW1B){                    src = W1 + (size_t)HID*HID;   w=g_w1b; K=HID; }
    else if ((i -= NW1B) < NW1C){                    src = W1 + (size_t)2*HID*HID; w=g_w1c; K=ED; }
    else if ((i -= NW1C) < NW2){                     src = W2;                     w=g_w2t; K=HID; }
    else if ((i -= NW2)  < NW3){                     src = W3;                     w=g_w3t; K=KC3; }
    else { i -= NW3;                                 src = W4;                     w=g_w4t; K=HID; }
    int k = i / HID, n = i % HID;
    w[(size_t)n*K + k] = __float2half(src[i] * WSC);
}
__global__ void k_split_ea(const float* __restrict__ s){
    int i = blockIdx.x * blockDim.x + threadIdx.x;
    if (i < NE*ED) g_ea[i] = __float2half(s[i]);
}
// decode edge_index (int64 vs int32 defensive) + zero agg
__global__ void k_decode_zero(const void* __restrict__ ei_raw){
    int i = blockIdx.x * blockDim.x + threadIdx.x;
    if (i < 2*NE){
        const long long* p64 = (const long long*)ei_raw;
        bool is64 = true;
        #pragma unroll
        for (int j = 0; j < 4; j++){
            long long v = p64[j];
            if (v < 0 || v >= NN) is64 = false;
        }
        g_ei[i] = is64 ? (int)p64[i] : ((const int*)ei_raw)[i];
    }
    if (i < NN*HID) g_agg[i] = 0.f;
}
__global__ void k_split_agg(){
    int i = blockIdx.x * blockDim.x + threadIdx.x;
    if (i < NN*HID) g_agg_h[i] = __float2half(g_agg[i]);
}

// ---------------- fp16 GEMM, BN=128, BK=64, 3-stage cp.async ----------------
// MODE 7: [P|Q] = x @ [W1a|W1b]                      (fp32 accum)
// MODE 1: h = mish(ea@W1c + P[src] + Q[dst] + b1)    (fp16 accum probe)
// MODE 2: msg = mish(h @ W2 + b2); RED scatter       (fp16 accum probe)
// MODE 3: u = mish([x|agg_h] @ W3 + b3)              (fp32 accum)
// MODE 4: y = x + u @ W4 + b4                        (fp32 accum)
template<int MODE>
__global__ __launch_bounds__(256, 2)
void gemm_kernel(const float* __restrict__ bias, const float* __restrict__ xres)
{
    constexpr int KTOT  = (MODE==1) ? ED : (MODE==3) ? KC3 : HID;
    constexpr int NCK   = KTOT / BK;
    constexpr bool HAS_BIAS = (MODE != 7);
    constexpr bool F16ACC   = (MODE==1 || MODE==2);

    extern __shared__ __align__(16) char smem_raw[];
    fp16* sm = (fp16*)smem_raw;
    __shared__ int sSrc[BM];
    __shared__ int sDst[BM];

    const int tid = threadIdx.x;
    const int n0  = blockIdx.x * BN;
    const int m0  = blockIdx.y * BM;

    if constexpr (MODE==1 || MODE==2){
        if (tid < BM){
            if (MODE == 1) sSrc[tid] = g_ei[m0 + tid];
            sDst[tid] = g_ei[NE + m0 + tid];
        }
    }

    const int wid = tid >> 5, lane = tid & 31;
    const int wm  = wid >> 1, wn = wid & 1;   // 4x2 warp grid, warp tile 32x64
    const int g   = lane >> 2, t = lane & 3;

    float acc[2][8][4];
    #pragma unroll
    for (int a = 0; a < 2; a++)
        #pragma unroll
        for (int b = 0; b < 8; b++)
            #pragma unroll
            for (int c = 0; c < 4; c++) acc[a][b][c] = 0.f;

    const fp16 *W;
    if      constexpr (MODE==1){ W = g_w1c; }
    else if constexpr (MODE==2){ W = g_w2t; }
    else if constexpr (MODE==3){ W = g_w3t; }
    else if constexpr (MODE==4){ W = g_w4t; }
    else { W = (n0 < HID) ? g_w1a : g_w1b; }
    const int nW = (MODE==7 && n0 >= HID) ? (n0 - HID) : n0;

    auto load_chunk = [&](int kc, int st){
        const int k0 = kc * BK;
        fp16* stg = sm + st*STG;
        // A: 128x64 fp16 = 1024 16B-chunks -> 4 per thread
        #pragma unroll
        for (int j = 0; j < 4; j++){
            int p = tid + j*256;
            int r = p >> 3, c = (p & 7) * 8;
            int k = k0 + c;
            const fp16 *pa;
            if constexpr (MODE==1){
                pa = g_ea + (size_t)(m0 + r)*ED + k;
            } else if constexpr (MODE==2){
                pa = g_h + (size_t)(m0 + r)*HID + k;
            } else if constexpr (MODE==3){
                int node = min(m0 + r, NN-1);
                if (k < HID) pa = g_x     + (size_t)node*HID + k;
                else         pa = g_agg_h + (size_t)node*HID + (k - HID);
            } else if constexpr (MODE==4){
                int node = min(m0 + r, NN-1);
                pa = g_u + (size_t)node*HID + k;
            } else {
                int node = min(m0 + r, NN-1);
                pa = g_x + (size_t)node*HID + k;
            }
            cp16(smem_u32(stg + r*BKP + c), pa);
        }
        // B: 128x64 = 1024 chunks -> 4 per thread
        #pragma unroll
        for (int j = 0; j < 4; j++){
            int p = tid + j*256;
            int r = p >> 3, c = (p & 7) * 8;
            size_t o = (size_t)(nW + r)*KTOT + k0 + c;
            cp16(smem_u32(stg + ASZ + r*BKP + c), W + o);
        }
        CP_COMMIT();
    };

    // prologue: stages 0 and 1
    load_chunk(0, 0);
    if (NCK > 1) load_chunk(1, 1);

    for (int kc = 0; kc < NCK; ++kc){
        if (kc + 1 < NCK) CP_WAIT1();   // chunk kc complete (newest group may be in flight)
        else              CP_WAIT0();
        __syncthreads();                // all warps done with stage (kc+2)%3's old data
        if (kc + 2 < NCK) load_chunk(kc + 2, (kc + 2) % NSTAGE);

        fp16* stg = sm + (kc % NSTAGE)*STG;
        fp16* sA  = stg;
        fp16* sB  = stg + ASZ;

        #pragma unroll
        for (int ks = 0; ks < 4; ++ks){
            const int kk = ks * 16;
            unsigned af[2][4];
            #pragma unroll
            for (int mt = 0; mt < 2; ++mt){
                int row = wm*32 + mt*16 + (lane & 7) + ((lane >> 3) & 1) * 8;
                int col = kk + (lane >> 4) * 8;
                ldsm_x4(af[mt][0], af[mt][1], af[mt][2], af[mt][3],
                        smem_u32(sA + row*BKP + col));
            }
            unsigned bf[8][2];
            #pragma unroll
            for (int np = 0; np < 4; ++np){
                int ntl = 2*np + (lane >> 4);
                int row = wn*64 + ntl*8 + (lane & 7);
                int col = kk + ((lane >> 3) & 1) * 8;
                unsigned r0, r1, r2, r3;
                ldsm_x4(r0, r1, r2, r3, smem_u32(sB + row*BKP + col));
                bf[2*np][0]=r0; bf[2*np][1]=r1; bf[2*np+1][0]=r2; bf[2*np+1][1]=r3;
            }
            #pragma unroll
            for (int mt = 0; mt < 2; ++mt)
                #pragma unroll
                for (int nt = 0; nt < 8; ++nt){
                    if constexpr (F16ACC)
                        mma_f16h(acc[mt][nt], af[mt][0], af[mt][1], af[mt][2], af[mt][3],
                                 bf[nt][0], bf[nt][1]);
                    else
                        mma_f16(acc[mt][nt], af[mt][0], af[mt][1], af[mt][2], af[mt][3],
                                bf[nt][0], bf[nt][1]);
                }
        }
    }

    // ---- epilogue (scale by WINV) ----
    #pragma unroll
    for (int mt = 0; mt < 2; ++mt){
        const int rl0 = wm*32 + mt*16 + g;
        const int rl1 = rl0 + 8;
        int s0 = 0, s1 = 0, d0 = 0, d1 = 0;
        if constexpr (MODE==1){ s0 = sSrc[rl0]; s1 = sSrc[rl1]; d0 = sDst[rl0]; d1 = sDst[rl1]; }
        if constexpr (MODE==2){ d0 = sDst[rl0]; d1 = sDst[rl1]; }
        #pragma unroll
        for (int nt = 0; nt < 8; ++nt){
            const int col = n0 + wn*64 + nt*8 + t*2;
            float bv0 = 0.f, bv1 = 0.f;
            if constexpr (HAS_BIAS){ bv0 = bias[col]; bv1 = bias[col+1]; }
            float v00 = acc[mt][nt][0]*WINV + bv0;
            float v01 = acc[mt][nt][1]*WINV + bv1;
            float v10 = acc[mt][nt][2]*WINV + bv0;
            float v11 = acc[mt][nt][3]*WINV + bv1;
            if constexpr (MODE==1){
                float2 p0 = *(const float2*)&g_P[(size_t)s0*HID + col];
                float2 q0 = *(const float2*)&g_Q[(size_t)d0*HID + col];
                float2 p1 = *(const float2*)&g_P[(size_t)s1*HID + col];
                float2 q1 = *(const float2*)&g_Q[(size_t)d1*HID + col];
                v00 = mishf(v00 + p0.x + q0.x);
                v01 = mishf(v01 + p0.y + q0.y);
                v10 = mishf(v10 + p1.x + q1.x);
                v11 = mishf(v11 + p1.y + q1.y);
                size_t o0 = (size_t)(m0+rl0)*HID + col;
                size_t o1 = (size_t)(m0+rl1)*HID + col;
                *(uint32_t*)&g_h[o0] = pack2h(__float2half(v00), __float2half(v01));
                *(uint32_t*)&g_h[o1] = pack2h(__float2half(v10), __float2half(v11));
            } else if constexpr (MODE==2){
                v00 = mishf(v00); v01 = mishf(v01); v10 = mishf(v10); v11 = mishf(v11);
                float p00 = __shfl_xor_sync(0xffffffffu, v00, 1);
                float p01 = __shfl_xor_sync(0xffffffffu, v01, 1);
                float p10 = __shfl_xor_sync(0xffffffffu, v10, 1);
                float p11 = __shfl_xor_sync(0xffffffffu, v11, 1);
                if ((t & 1) == 0){
                    atomicAdd((float4*)&g_agg[(size_t)d0*HID + col], make_float4(v00, v01, p00, p01));
                    atomicAdd((float4*)&g_agg[(size_t)d1*HID + col], make_float4(v10, v11, p10, p11));
                }
            } else if constexpr (MODE==3){
                const int r0i = m0 + rl0, r1i = m0 + rl1;
                if (r0i < NN){
                    size_t o = (size_t)r0i*HID + col;
                    *(uint32_t*)&g_u[o] = pack2h(__float2half(mishf(v00)), __float2half(mishf(v01)));
                }
                if (r1i < NN){
                    size_t o = (size_t)r1i*HID + col;
                    *(uint32_t*)&g_u[o] = pack2h(__float2half(mishf(v10)), __float2half(mishf(v11)));
                }
            } else if constexpr (MODE==4){
                const int r0i = m0 + rl0, r1i = m0 + rl1;
                if (r0i < NN){
                    float2 xv = *(const float2*)&xres[(size_t)r0i*HID + col];
                    *(float2*)&g_y[(size_t)r0i*HID + col] = make_float2(v00 + xv.x, v01 + xv.y);
                }
                if (r1i < NN){
                    float2 xv = *(const float2*)&xres[(size_t)r1i*HID + col];
                    *(float2*)&g_y[(size_t)r1i*HID + col] = make_float2(v10 + xv.x, v11 + xv.y);
                }
            } else { // MODE 7
                float* dst = (n0 < HID) ? g_P : g_Q;
                const int cw = nW + wn*64 + nt*8 + t*2;
                const int r0i = m0 + rl0, r1i = m0 + rl1;
                if (r0i < NN)
                    *(float2*)&dst[(size_t)r0i*HID + cw] = make_float2(v00, v01);
                if (r1i < NN)
                    *(float2*)&dst[(size_t)r1i*HID + cw] = make_float2(v10, v11);
            }
        }
    }
}

// ---------------- LayerNorm ----------------
__global__ __launch_bounds__(128)
void ln_kernel(const float* __restrict__ gamma, const float* __restrict__ beta,
               float* __restrict__ out)
{
    const int row = blockIdx.x, tid = threadIdx.x;
    float4 v = *((const float4*)(g_y + (size_t)row*HID) + tid);
    float s  = v.x + v.y + v.z + v.w;
    float ss = fmaf(v.x, v.x, fmaf(v.y, v.y, fmaf(v.z, v.z, v.w*v.w)));
    #pragma unroll
    for (int o = 16; o > 0; o >>= 1){
        s  += __shfl_xor_sync(0xffffffffu, s,  o);
        ss += __shfl_xor_sync(0xffffffffu, ss, o);
    }
    __shared__ float sh_s[4], sh_ss[4];
    if ((tid & 31) == 0){ sh_s[tid >> 5] = s; sh_ss[tid >> 5] = ss; }
    __syncthreads();
    s  = sh_s[0]  + sh_s[1]  + sh_s[2]  + sh_s[3];
    ss = sh_ss[0] + sh_ss[1] + sh_ss[2] + sh_ss[3];
    const float mu  = s * (1.f / HID);
    const float var = ss * (1.f / HID) - mu * mu;
    const float inv = rsqrtf(var + 1e-5f);
    float4 gm = ((const float4*)gamma)[tid];
    float4 bt = ((const float4*)beta)[tid];
    float4 o;
    o.x = (v.x - mu) * inv * gm.x + bt.x;
    o.y = (v.y - mu) * inv * gm.y + bt.y;
    o.z = (v.z - mu) * inv * gm.z + bt.z;
    o.w = (v.w - mu) * inv * gm.w + bt.w;
    *((float4*)(out + (size_t)row*HID) + tid) = o;
}

// ---------------- launch ----------------
extern "C" void kernel_launch(void* const* d_in, const int* in_sizes, int n_in,
                              void* d_out, int out_size)
{
    (void)in_sizes; (void)n_in; (void)out_size;
    const float* x     = (const float*)d_in[0];
    const void*  ei    = d_in[1];
    const float* ea    = (const float*)d_in[2];
    const float* W1    = (const float*)d_in[3];
    const float* b1    = (const float*)d_in[4];
    const float* W2    = (const float*)d_in[5];
    const float* b2    = (const float*)d_in[6];
    const float* W3    = (const float*)d_in[7];
    const float* b3    = (const float*)d_in[8];
    const float* W4    = (const float*)d_in[9];
    const float* b4    = (const float*)d_in[10];
    const float* gamma = (const float*)d_in[11];
    const float* beta  = (const float*)d_in[12];
    float* out = (float*)d_out;

    cudaFuncSetAttribute(gemm_kernel<1>, cudaFuncAttributeMaxDynamicSharedMemorySize, SMEM_BYTES);
    cudaFuncSetAttribute(gemm_kernel<2>, cudaFuncAttributeMaxDynamicSharedMemorySize, SMEM_BYTES);
    cudaFuncSetAttribute(gemm_kernel<3>, cudaFuncAttributeMaxDynamicSharedMemorySize, SMEM_BYTES);
    cudaFuncSetAttribute(gemm_kernel<4>, cudaFuncAttributeMaxDynamicSharedMemorySize, SMEM_BYTES);
    cudaFuncSetAttribute(gemm_kernel<7>, cudaFuncAttributeMaxDynamicSharedMemorySize, SMEM_BYTES);

    k_split_all  <<<(SPLIT_ALL_TOT + 255)/256, 256>>>(x, W1, W2, W3, W4);   // 1
    k_split_ea   <<<(NE*ED + 255)/256, 256>>>(ea);                          // 2
    k_decode_zero<<<(NN*HID + 255)/256, 256>>>(ei);                         // 3

    dim3 gPQ(2*HID/BN, (NN + BM - 1)/BM);    // (8, 157)
    dim3 gE(HID/BN, NE/BM);                  // (4, 2500)
    dim3 gN(HID/BN, (NN + BM - 1)/BM);       // (4, 157)
    gemm_kernel<7><<<gPQ, 256, SMEM_BYTES>>>(nullptr, nullptr);  // 4: P|Q
    gemm_kernel<1><<<gE, 256, SMEM_BYTES>>>(b1, nullptr);        // 5: h
    gemm_kernel<2><<<gE, 256, SMEM_BYTES>>>(b2, nullptr);        // 6: messages+scatter
    k_split_agg  <<<(NN*HID + 255)/256, 256>>>();                // 7
    gemm_kernel<3><<<gN, 256, SMEM_BYTES>>>(b3, nullptr);        // 8: u
    gemm_kernel<4><<<gN, 256, SMEM_BYTES>>>(b4, x);              // 9: y
    ln_kernel<<<NN, 128>>>(gamma, beta, out);                    // 10
}

// round 15
// speedup vs baseline: 1.1769x; 1.1769x over previous
#include <cuda_runtime.h>
#include <cuda_fp16.h>
#include <math.h>
#include <stdint.h>

using fp16 = __half;

constexpr int NN  = 20000;      // nodes
constexpr int NE  = 320000;     // edges
constexpr int HID = 512;
constexpr int ED  = 64;
constexpr int KC3 = 2*HID;      // 1024

constexpr int BM = 128, BN = 128, BK = 64, PAD = 8, BKP = BK + PAD;

constexpr int ASZ = BM*BKP;             // A tile
constexpr int BSZ = BN*BKP;             // B tile
constexpr int STG = ASZ + BSZ;          // per-stage elements
constexpr int NSTAGE = 3;
constexpr int SMEM_BYTES = NSTAGE*STG*(int)sizeof(fp16);   // 110592

constexpr float WSC  = 32.0f;           // weight pre-scale (power of 2, exact)
constexpr float WINV = 1.0f/32.0f;

// ---------------- device scratch ----------------
__device__ fp16 g_x[NN*HID];
__device__ fp16 g_ea[NE*ED];
__device__ fp16 g_w1a[HID*HID];
__device__ fp16 g_w1b[HID*HID];
__device__ fp16 g_w1c[HID*ED];
__device__ fp16 g_w2t[HID*HID];
__device__ fp16 g_w3t[HID*KC3];
__device__ fp16 g_w4t[HID*HID];
__device__ int   g_ei[2*NE];
__device__ float g_P[NN*HID];
__device__ float g_Q[NN*HID];
__device__ fp16  g_h[(size_t)NE*HID];
__device__ float g_agg[NN*HID];
__device__ fp16  g_agg_h[NN*HID];
__device__ fp16  g_u[NN*HID];
__device__ float g_y[NN*HID];

// ---------------- helpers ----------------
__device__ __forceinline__ float mishf(float x){
    float t   = __expf(fminf(x, 15.f));
    float num = t * (t + 2.f);
    return x * __fdividef(num, num + 2.f);
}
__device__ __forceinline__ unsigned smem_u32(const void* p){
    return (unsigned)__cvta_generic_to_shared(p);
}
__device__ __forceinline__ void ldsm_x4(unsigned &r0, unsigned &r1, unsigned &r2, unsigned &r3, unsigned addr){
    asm volatile("ldmatrix.sync.aligned.m8n8.x4.shared.b16 {%0,%1,%2,%3}, [%4];"
                 : "=r"(r0), "=r"(r1), "=r"(r2), "=r"(r3) : "r"(addr));
}
__device__ __forceinline__ void mma_f16(float* c, unsigned a0, unsigned a1, unsigned a2, unsigned a3,
                                        unsigned b0, unsigned b1){
    asm volatile("mma.sync.aligned.m16n8k16.row.col.f32.f16.f16.f32 "
                 "{%0,%1,%2,%3}, {%4,%5,%6,%7}, {%8,%9}, {%0,%1,%2,%3};"
                 : "+f"(c[0]), "+f"(c[1]), "+f"(c[2]), "+f"(c[3])
                 : "r"(a0), "r"(a1), "r"(a2), "r"(a3), "r"(b0), "r"(b1));
}
__device__ __forceinline__ uint32_t pack2h(fp16 a, fp16 b){
    __half2 p; p.x = a; p.y = b;
    return *(uint32_t*)&p;
}
__device__ __forceinline__ void cp16(uint32_t dst, const void* src){
    asm volatile("cp.async.cg.shared.global [%0], [%1], 16;" :: "r"(dst), "l"(src));
}
#define CP_COMMIT() asm volatile("cp.async.commit_group;" ::: "memory")
#define CP_WAIT1()  asm volatile("cp.async.wait_group 1;" ::: "memory")
#define CP_WAIT0()  asm volatile("cp.async.wait_group 0;" ::: "memory")

// ---------------- prep kernels (fused) ----------------
constexpr int NX   = NN*HID;
constexpr int NW1A = HID*HID;
constexpr int NW1B = HID*HID;
constexpr int NW1C = ED*HID;
constexpr int NW2  = HID*HID;
constexpr int NW3  = KC3*HID;
constexpr int NW4  = HID*HID;
constexpr int SPLIT_ALL_TOT = NX + NW1A + NW1B + NW1C + NW2 + NW3 + NW4;

__global__ void k_split_all(const float* __restrict__ x,
                            const float* __restrict__ W1,
                            const float* __restrict__ W2,
                            const float* __restrict__ W3,
                            const float* __restrict__ W4){
    int i = blockIdx.x * blockDim.x + threadIdx.x;
    if (i >= SPLIT_ALL_TOT) return;
    if (i < NX){
        g_x[i] = __float2half(x[i]);
        return;
    }
    i -= NX;
    const float* src; fp16 *w; int K;
    if      (i < NW1A){                              src = W1;                     w=g_w1a; K=HID; }
    else if ((i -= NW1A) < NW1B){                    src = W1 + (size_t)HID*HID;   w=g_w1b; K=HID; }
    else if ((i -= NW1B) < NW1C){                    src = W1 + (size_t)2*HID*HID; w=g_w1c; K=ED; }
    else if ((i -= NW1C) < NW2){                     src = W2;                     w=g_w2t; K=HID; }
    else if ((i -= NW2)  < NW3){                     src = W3;                     w=g_w3t; K=KC3; }
    else { i -= NW3;                                 src = W4;                     w=g_w4t; K=HID; }
    int k = i / HID, n = i % HID;
    w[(size_t)n*K + k] = __float2half(src[i] * WSC);
}
__global__ void k_split_ea(const float* __restrict__ s){
    int i = blockIdx.x * blockDim.x + threadIdx.x;
    if (i < NE*ED) g_ea[i] = __float2half(s[i]);
}
// decode edge_index (int64 vs int32 defensive) + zero agg
__global__ void k_decode_zero(const void* __restrict__ ei_raw){
    int i = blockIdx.x * blockDim.x + threadIdx.x;
    if (i < 2*NE){
        const long long* p64 = (const long long*)ei_raw;
        bool is64 = true;
        #pragma unroll
        for (int j = 0; j < 4; j++){
            long long v = p64[j];
            if (v < 0 || v >= NN) is64 = false;
        }
        g_ei[i] = is64 ? (int)p64[i] : ((const int*)ei_raw)[i];
    }
    if (i < NN*HID) g_agg[i] = 0.f;
}
__global__ void k_split_agg(){
    int i = blockIdx.x * blockDim.x + threadIdx.x;
    if (i < NN*HID) g_agg_h[i] = __float2half(g_agg[i]);
}

// ---------------- fp16 GEMM, BN=128, BK=64, 3-stage cp.async, fp32 accum ----------------
// MODE 7: [P|Q] = x @ [W1a|W1b]
// MODE 1: h = mish(ea@W1c + P[src] + Q[dst] + b1)
// MODE 2: msg = mish(h @ W2 + b2); float4 RED scatter into agg[dst]
// MODE 3: u = mish([x|agg_h] @ W3 + b3)
// MODE 4: y = x + u @ W4 + b4
template<int MODE>
__global__ __launch_bounds__(256, 2)
void gemm_kernel(const float* __restrict__ bias, const float* __restrict__ xres)
{
    constexpr int KTOT  = (MODE==1) ? ED : (MODE==3) ? KC3 : HID;
    constexpr int NCK   = KTOT / BK;
    constexpr bool HAS_BIAS = (MODE != 7);

    extern __shared__ __align__(16) char smem_raw[];
    fp16* sm = (fp16*)smem_raw;
    __shared__ int sSrc[BM];
    __shared__ int sDst[BM];

    const int tid = threadIdx.x;
    const int n0  = blockIdx.x * BN;
    const int m0  = blockIdx.y * BM;

    if constexpr (MODE==1 || MODE==2){
        if (tid < BM){
            if (MODE == 1) sSrc[tid] = g_ei[m0 + tid];
            sDst[tid] = g_ei[NE + m0 + tid];
        }
    }

    const int wid = tid >> 5, lane = tid & 31;
    const int wm  = wid >> 1, wn = wid & 1;   // 4x2 warp grid, warp tile 32x64
    const int g   = lane >> 2, t = lane & 3;

    float acc[2][8][4];
    #pragma unroll
    for (int a = 0; a < 2; a++)
        #pragma unroll
        for (int b = 0; b < 8; b++)
            #pragma unroll
            for (int c = 0; c < 4; c++) acc[a][b][c] = 0.f;

    const fp16 *W;
    if      constexpr (MODE==1){ W = g_w1c; }
    else if constexpr (MODE==2){ W = g_w2t; }
    else if constexpr (MODE==3){ W = g_w3t; }
    else if constexpr (MODE==4){ W = g_w4t; }
    else { W = (n0 < HID) ? g_w1a : g_w1b; }
    const int nW = (MODE==7 && n0 >= HID) ? (n0 - HID) : n0;

    auto load_chunk = [&](int kc, int st){
        const int k0 = kc * BK;
        fp16* stg = sm + st*STG;
        // A: 128x64 fp16 = 1024 16B-chunks -> 4 per thread
        #pragma unroll
        for (int j = 0; j < 4; j++){
            int p = tid + j*256;
            int r = p >> 3, c = (p & 7) * 8;
            int k = k0 + c;
            const fp16 *pa;
            if constexpr (MODE==1){
                pa = g_ea + (size_t)(m0 + r)*ED + k;
            } else if constexpr (MODE==2){
                pa = g_h + (size_t)(m0 + r)*HID + k;
            } else if constexpr (MODE==3){
                int node = min(m0 + r, NN-1);
                if (k < HID) pa = g_x     + (size_t)node*HID + k;
                else         pa = g_agg_h + (size_t)node*HID + (k - HID);
            } else if constexpr (MODE==4){
                int node = min(m0 + r, NN-1);
                pa = g_u + (size_t)node*HID + k;
            } else {
                int node = min(m0 + r, NN-1);
                pa = g_x + (size_t)node*HID + k;
            }
            cp16(smem_u32(stg + r*BKP + c), pa);
        }
        // B: 128x64 = 1024 chunks -> 4 per thread
        #pragma unroll
        for (int j = 0; j < 4; j++){
            int p = tid + j*256;
            int r = p >> 3, c = (p & 7) * 8;
            size_t o = (size_t)(nW + r)*KTOT + k0 + c;
            cp16(smem_u32(stg + ASZ + r*BKP + c), W + o);
        }
        CP_COMMIT();
    };

    // prologue: stages 0 and 1
    load_chunk(0, 0);
    if (NCK > 1) load_chunk(1, 1);

    for (int kc = 0; kc < NCK; ++kc){
        if (kc + 1 < NCK) CP_WAIT1();   // chunk kc complete (newest group may be in flight)
        else              CP_WAIT0();
        __syncthreads();                // all warps done with stage (kc+2)%3's old data
        if (kc + 2 < NCK) load_chunk(kc + 2, (kc + 2) % NSTAGE);

        fp16* stg = sm + (kc % NSTAGE)*STG;
        fp16* sA  = stg;
        fp16* sB  = stg + ASZ;

        #pragma unroll
        for (int ks = 0; ks < 4; ++ks){
            const int kk = ks * 16;
            unsigned af[2][4];
            #pragma unroll
            for (int mt = 0; mt < 2; ++mt){
                int row = wm*32 + mt*16 + (lane & 7) + ((lane >> 3) & 1) * 8;
                int col = kk + (lane >> 4) * 8;
                ldsm_x4(af[mt][0], af[mt][1], af[mt][2], af[mt][3],
                        smem_u32(sA + row*BKP + col));
            }
            unsigned bf[8][2];
            #pragma unroll
            for (int np = 0; np < 4; ++np){
                int ntl = 2*np + (lane >> 4);
                int row = wn*64 + ntl*8 + (lane & 7);
                int col = kk + ((lane >> 3) & 1) * 8;
                unsigned r0, r1, r2, r3;
                ldsm_x4(r0, r1, r2, r3, smem_u32(sB + row*BKP + col));
                bf[2*np][0]=r0; bf[2*np][1]=r1; bf[2*np+1][0]=r2; bf[2*np+1][1]=r3;
            }
            #pragma unroll
            for (int mt = 0; mt < 2; ++mt)
                #pragma unroll
                for (int nt = 0; nt < 8; ++nt)
                    mma_f16(acc[mt][nt], af[mt][0], af[mt][1], af[mt][2], af[mt][3],
                            bf[nt][0], bf[nt][1]);
        }
    }

    // ---- epilogue (scale by WINV) ----
    #pragma unroll
    for (int mt = 0; mt < 2; ++mt){
        const int rl0 = wm*32 + mt*16 + g;
        const int rl1 = rl0 + 8;
        int s0 = 0, s1 = 0, d0 = 0, d1 = 0;
        if constexpr (MODE==1){ s0 = sSrc[rl0]; s1 = sSrc[rl1]; d0 = sDst[rl0]; d1 = sDst[rl1]; }
        if constexpr (MODE==2){ d0 = sDst[rl0]; d1 = sDst[rl1]; }
        #pragma unroll
        for (int nt = 0; nt < 8; ++nt){
            const int col = n0 + wn*64 + nt*8 + t*2;
            float bv0 = 0.f, bv1 = 0.f;
            if constexpr (HAS_BIAS){ bv0 = bias[col]; bv1 = bias[col+1]; }
            float v00 = acc[mt][nt][0]*WINV + bv0;
            float v01 = acc[mt][nt][1]*WINV + bv1;
            float v10 = acc[mt][nt][2]*WINV + bv0;
            float v11 = acc[mt][nt][3]*WINV + bv1;
            if constexpr (MODE==1){
                float2 p0 = *(const float2*)&g_P[(size_t)s0*HID + col];
                float2 q0 = *(const float2*)&g_Q[(size_t)d0*HID + col];
                float2 p1 = *(const float2*)&g_P[(size_t)s1*HID + col];
                float2 q1 = *(const float2*)&g_Q[(size_t)d1*HID + col];
                v00 = mishf(v00 + p0.x + q0.x);
                v01 = mishf(v01 + p0.y + q0.y);
                v10 = mishf(v10 + p1.x + q1.x);
                v11 = mishf(v11 + p1.y + q1.y);
                size_t o0 = (size_t)(m0+rl0)*HID + col;
                size_t o1 = (size_t)(m0+rl1)*HID + col;
                *(uint32_t*)&g_h[o0] = pack2h(__float2half(v00), __float2half(v01));
                *(uint32_t*)&g_h[o1] = pack2h(__float2half(v10), __float2half(v11));
            } else if constexpr (MODE==2){
                v00 = mishf(v00); v01 = mishf(v01); v10 = mishf(v10); v11 = mishf(v11);
                float p00 = __shfl_xor_sync(0xffffffffu, v00, 1);
                float p01 = __shfl_xor_sync(0xffffffffu, v01, 1);
                float p10 = __shfl_xor_sync(0xffffffffu, v10, 1);
                float p11 = __shfl_xor_sync(0xffffffffu, v11, 1);
                if ((t & 1) == 0){
                    atomicAdd((float4*)&g_agg[(size_t)d0*HID + col], make_float4(v00, v01, p00, p01));
                    atomicAdd((float4*)&g_agg[(size_t)d1*HID + col], make_float4(v10, v11, p10, p11));
                }
            } else if constexpr (MODE==3){
                const int r0i = m0 + rl0, r1i = m0 + rl1;
                if (r0i < NN){
                    size_t o = (size_t)r0i*HID + col;
                    *(uint32_t*)&g_u[o] = pack2h(__float2half(mishf(v00)), __float2half(mishf(v01)));
                }
                if (r1i < NN){
                    size_t o = (size_t)r1i*HID + col;
                    *(uint32_t*)&g_u[o] = pack2h(__float2half(mishf(v10)), __float2half(mishf(v11)));
                }
            } else if constexpr (MODE==4){
                const int r0i = m0 + rl0, r1i = m0 + rl1;
                if (r0i < NN){
                    float2 xv = *(const float2*)&xres[(size_t)r0i*HID + col];
                    *(float2*)&g_y[(size_t)r0i*HID + col] = make_float2(v00 + xv.x, v01 + xv.y);
                }
                if (r1i < NN){
                    float2 xv = *(const float2*)&xres[(size_t)r1i*HID + col];
                    *(float2*)&g_y[(size_t)r1i*HID + col] = make_float2(v10 + xv.x, v11 + xv.y);
                }
            } else { // MODE 7
                float* dst = (n0 < HID) ? g_P : g_Q;
                const int cw = nW + wn*64 + nt*8 + t*2;
                const int r0i = m0 + rl0, r1i = m0 + rl1;
                if (r0i < NN)
                    *(float2*)&dst[(size_t)r0i*HID + cw] = make_float2(v00, v01);
                if (r1i < NN)
                    *(float2*)&dst[(size_t)r1i*HID + cw] = make_float2(v10, v11);
            }
        }
    }
}

// ---------------- LayerNorm ----------------
__global__ __launch_bounds__(128)
void ln_kernel(const float* __restrict__ gamma, const float* __restrict__ beta,
               float* __restrict__ out)
{
    const int row = blockIdx.x, tid = threadIdx.x;
    float4 v = *((const float4*)(g_y + (size_t)row*HID) + tid);
    float s  = v.x + v.y + v.z + v.w;
    float ss = fmaf(v.x, v.x, fmaf(v.y, v.y, fmaf(v.z, v.z, v.w*v.w)));
    #pragma unroll
    for (int o = 16; o > 0; o >>= 1){
        s  += __shfl_xor_sync(0xffffffffu, s,  o);
        ss += __shfl_xor_sync(0xffffffffu, ss, o);
    }
    __shared__ float sh_s[4], sh_ss[4];
    if ((tid & 31) == 0){ sh_s[tid >> 5] = s; sh_ss[tid >> 5] = ss; }
    __syncthreads();
    s  = sh_s[0]  + sh_s[1]  + sh_s[2]  + sh_s[3];
    ss = sh_ss[0] + sh_ss[1] + sh_ss[2] + sh_ss[3];
    const float mu  = s * (1.f / HID);
    const float var = ss * (1.f / HID) - mu * mu;
    const float inv = rsqrtf(var + 1e-5f);
    float4 gm = ((const float4*)gamma)[tid];
    float4 bt = ((const float4*)beta)[tid];
    float4 o;
    o.x = (v.x - mu) * inv * gm.x + bt.x;
    o.y = (v.y - mu) * inv * gm.y + bt.y;
    o.z = (v.z - mu) * inv * gm.z + bt.z;
    o.w = (v.w - mu) * inv * gm.w + bt.w;
    *((float4*)(out + (size_t)row*HID) + tid) = o;
}

// ---------------- launch ----------------
extern "C" void kernel_launch(void* const* d_in, const int* in_sizes, int n_in,
                              void* d_out, int out_size)
{
    (void)in_sizes; (void)n_in; (void)out_size;
    const float* x     = (const float*)d_in[0];
    const void*  ei    = d_in[1];
    const float* ea    = (const float*)d_in[2];
    const float* W1    = (const float*)d_in[3];
    const float* b1    = (const float*)d_in[4];
    const float* W2    = (const float*)d_in[5];
    const float* b2    = (const float*)d_in[6];
    const float* W3    = (const float*)d_in[7];
    const float* b3    = (const float*)d_in[8];
    const float* W4    = (const float*)d_in[9];
    const float* b4    = (const float*)d_in[10];
    const float* gamma = (const float*)d_in[11];
    const float* beta  = (const float*)d_in[12];
    float* out = (float*)d_out;

    cudaFuncSetAttribute(gemm_kernel<1>, cudaFuncAttributeMaxDynamicSharedMemorySize, SMEM_BYTES);
    cudaFuncSetAttribute(gemm_kernel<2>, cudaFuncAttributeMaxDynamicSharedMemorySize, SMEM_BYTES);
    cudaFuncSetAttribute(gemm_kernel<3>, cudaFuncAttributeMaxDynamicSharedMemorySize, SMEM_BYTES);
    cudaFuncSetAttribute(gemm_kernel<4>, cudaFuncAttributeMaxDynamicSharedMemorySize, SMEM_BYTES);
    cudaFuncSetAttribute(gemm_kernel<7>, cudaFuncAttributeMaxDynamicSharedMemorySize, SMEM_BYTES);

    k_split_all  <<<(SPLIT_ALL_TOT + 255)/256, 256>>>(x, W1, W2, W3, W4);   // 1
    k_split_ea   <<<(NE*ED + 255)/256, 256>>>(ea);                          // 2
    k_decode_zero<<<(NN*HID + 255)/256, 256>>>(ei);                         // 3

    dim3 gPQ(2*HID/BN, (NN + BM - 1)/BM);    // (8, 157)
    dim3 gE(HID/BN, NE/BM);                  // (4, 2500)
    dim3 gN(HID/BN, (NN + BM - 1)/BM);       // (4, 157)
    gemm_kernel<7><<<gPQ, 256, SMEM_BYTES>>>(nullptr, nullptr);  // 4: P|Q
    gemm_kernel<1><<<gE, 256, SMEM_BYTES>>>(b1, nullptr);        // 5: h
    gemm_kernel<2><<<gE, 256, SMEM_BYTES>>>(b2, nullptr);        // 6: messages+scatter
    k_split_agg  <<<(NN*HID + 255)/256, 256>>>();                // 7
    gemm_kernel<3><<<gN, 256, SMEM_BYTES>>>(b3, nullptr);        // 8: u
    gemm_kernel<4><<<gN, 256, SMEM_BYTES>>>(b4, x);              // 9: y
    ln_kernel<<<NN, 128>>>(gamma, beta, out);                    // 10
}

// round 16
// speedup vs baseline: 1.2589x; 1.0697x over previous
#include <cuda_runtime.h>
#include <cuda_fp16.h>
#include <math.h>
#include <stdint.h>

using fp16 = __half;

constexpr int NN  = 20000;      // nodes
constexpr int NE  = 320000;     // edges
constexpr int HID = 512;
constexpr int ED  = 64;
constexpr int KC3 = 2*HID;      // 1024

constexpr int BM = 128, BN = 128, PAD = 8;
constexpr int NSTAGE = 3;

// per-BK smem sizes
constexpr int SMEM_BK64 = NSTAGE*( (BM+BN)*(64+PAD) )*(int)sizeof(fp16);  // 110592
constexpr int SMEM_BK32 = NSTAGE*( (BM+BN)*(32+PAD) )*(int)sizeof(fp16);  // 61440

constexpr float WSC  = 32.0f;           // weight pre-scale (power of 2, exact)
constexpr float WINV = 1.0f/32.0f;

// ---------------- device scratch ----------------
__device__ fp16 g_x[NN*HID];
__device__ fp16 g_ea[NE*ED];
__device__ fp16 g_w1a[HID*HID];
__device__ fp16 g_w1b[HID*HID];
__device__ fp16 g_w1c[HID*ED];
__device__ fp16 g_w2t[HID*HID];
__device__ fp16 g_w3t[HID*KC3];
__device__ fp16 g_w4t[HID*HID];
__device__ int   g_ei[2*NE];
__device__ fp16  g_P[NN*HID];           // fp16: halves MODE1 gather traffic
__device__ fp16  g_Q[NN*HID];
__device__ fp16  g_h[(size_t)NE*HID];
__device__ float g_agg[NN*HID];
__device__ fp16  g_agg_h[NN*HID];
__device__ fp16  g_u[NN*HID];
__device__ float g_y[NN*HID];

// ---------------- helpers ----------------
__device__ __forceinline__ float mishf(float x){
    float t   = __expf(fminf(x, 15.f));
    float num = t * (t + 2.f);
    return x * __fdividef(num, num + 2.f);
}
__device__ __forceinline__ unsigned smem_u32(const void* p){
    return (unsigned)__cvta_generic_to_shared(p);
}
__device__ __forceinline__ void ldsm_x4(unsigned &r0, unsigned &r1, unsigned &r2, unsigned &r3, unsigned addr){
    asm volatile("ldmatrix.sync.aligned.m8n8.x4.shared.b16 {%0,%1,%2,%3}, [%4];"
                 : "=r"(r0), "=r"(r1), "=r"(r2), "=r"(r3) : "r"(addr));
}
__device__ __forceinline__ void mma_f16(float* c, unsigned a0, unsigned a1, unsigned a2, unsigned a3,
                                        unsigned b0, unsigned b1){
    asm volatile("mma.sync.aligned.m16n8k16.row.col.f32.f16.f16.f32 "
                 "{%0,%1,%2,%3}, {%4,%5,%6,%7}, {%8,%9}, {%0,%1,%2,%3};"
                 : "+f"(c[0]), "+f"(c[1]), "+f"(c[2]), "+f"(c[3])
                 : "r"(a0), "r"(a1), "r"(a2), "r"(a3), "r"(b0), "r"(b1));
}
__device__ __forceinline__ uint32_t pack2h(fp16 a, fp16 b){
    __half2 p; p.x = a; p.y = b;
    return *(uint32_t*)&p;
}
__device__ __forceinline__ void cp16(uint32_t dst, const void* src){
    asm volatile("cp.async.cg.shared.global [%0], [%1], 16;" :: "r"(dst), "l"(src));
}
#define CP_COMMIT() asm volatile("cp.async.commit_group;" ::: "memory")
#define CP_WAIT1()  asm volatile("cp.async.wait_group 1;" ::: "memory")
#define CP_WAIT0()  asm volatile("cp.async.wait_group 0;" ::: "memory")

// ---------------- prep kernels (fused) ----------------
constexpr int NX   = NN*HID;
constexpr int NW1A = HID*HID;
constexpr int NW1B = HID*HID;
constexpr int NW1C = ED*HID;
constexpr int NW2  = HID*HID;
constexpr int NW3  = KC3*HID;
constexpr int NW4  = HID*HID;
constexpr int SPLIT_ALL_TOT = NX + NW1A + NW1B + NW1C + NW2 + NW3 + NW4;

__global__ void k_split_all(const float* __restrict__ x,
                            const float* __restrict__ W1,
                            const float* __restrict__ W2,
                            const float* __restrict__ W3,
                            const float* __restrict__ W4){
    int i = blockIdx.x * blockDim.x + threadIdx.x;
    if (i >= SPLIT_ALL_TOT) return;
    if (i < NX){
        g_x[i] = __float2half(x[i]);
        return;
    }
    i -= NX;
    const float* src; fp16 *w; int K;
    if      (i < NW1A){                              src = W1;                     w=g_w1a; K=HID; }
    else if ((i -= NW1A) < NW1B){                    src = W1 + (size_t)HID*HID;   w=g_w1b; K=HID; }
    else if ((i -= NW1B) < NW1C){                    src = W1 + (size_t)2*HID*HID; w=g_w1c; K=ED; }
    else if ((i -= NW1C) < NW2){                     src = W2;                     w=g_w2t; K=HID; }
    else if ((i -= NW2)  < NW3){                     src = W3;                     w=g_w3t; K=KC3; }
    else { i -= NW3;                                 src = W4;                     w=g_w4t; K=HID; }
    int k = i / HID, n = i % HID;
    w[(size_t)n*K + k] = __float2half(src[i] * WSC);
}
__global__ void k_split_ea(const float* __restrict__ s){
    int i = blockIdx.x * blockDim.x + threadIdx.x;
    if (i < NE*ED) g_ea[i] = __float2half(s[i]);
}
// decode edge_index (int64 vs int32 defensive) + zero agg
__global__ void k_decode_zero(const void* __restrict__ ei_raw){
    int i = blockIdx.x * blockDim.x + threadIdx.x;
    if (i < 2*NE){
        const long long* p64 = (const long long*)ei_raw;
        bool is64 = true;
        #pragma unroll
        for (int j = 0; j < 4; j++){
            long long v = p64[j];
            if (v < 0 || v >= NN) is64 = false;
        }
        g_ei[i] = is64 ? (int)p64[i] : ((const int*)ei_raw)[i];
    }
    if (i < NN*HID) g_agg[i] = 0.f;
}
__global__ void k_split_agg(){
    int i = blockIdx.x * blockDim.x + threadIdx.x;
    if (i < NN*HID) g_agg_h[i] = __float2half(g_agg[i]);
}

// ---------------- fp16 GEMM, BN=128, per-mode BK, 3-stage cp.async ----------------
// MODE 7: [P|Q] = x @ [W1a|W1b]     (BK=64, fp16 P/Q out)
// MODE 1: h = mish(ea@W1c + P[src] + Q[dst] + b1)   (BK=32)
// MODE 2: msg = mish(h @ W2 + b2); RED scatter      (BK=32)
// MODE 3: u = mish([x|agg_h] @ W3 + b3)             (BK=64)
// MODE 4: y = x + u @ W4 + b4                       (BK=64)
template<int MODE, int BKT>
__global__ __launch_bounds__(256, 2)
void gemm_kernel(const float* __restrict__ bias, const float* __restrict__ xres)
{
    constexpr int KTOT  = (MODE==1) ? ED : (MODE==3) ? KC3 : HID;
    constexpr int NCK   = KTOT / BKT;
    constexpr int BKP_T = BKT + PAD;
    constexpr int ASZ_T = BM*BKP_T;
    constexpr int BSZ_T = BN*BKP_T;
    constexpr int STG_T = ASZ_T + BSZ_T;
    constexpr int CPT   = BKT/16;          // A(or B) 16B-chunks per thread
    constexpr int RSH   = (BKT==64) ? 3 : 2;
    constexpr int CMSK  = (BKT==64) ? 7 : 3;
    constexpr bool HAS_BIAS = (MODE != 7);

    extern __shared__ __align__(16) char smem_raw[];
    fp16* sm = (fp16*)smem_raw;
    __shared__ int sSrc[BM];
    __shared__ int sDst[BM];

    const int tid = threadIdx.x;
    const int n0  = blockIdx.x * BN;
    const int m0  = blockIdx.y * BM;

    if constexpr (MODE==1 || MODE==2){
        if (tid < BM){
            if (MODE == 1) sSrc[tid] = g_ei[m0 + tid];
            sDst[tid] = g_ei[NE + m0 + tid];
        }
    }

    const int wid = tid >> 5, lane = tid & 31;
    const int wm  = wid >> 1, wn = wid & 1;   // 4x2 warp grid, warp tile 32x64
    const int g   = lane >> 2, t = lane & 3;

    float acc[2][8][4];
    #pragma unroll
    for (int a = 0; a < 2; a++)
        #pragma unroll
        for (int b = 0; b < 8; b++)
            #pragma unroll
            for (int c = 0; c < 4; c++) acc[a][b][c] = 0.f;

    const fp16 *W;
    if      constexpr (MODE==1){ W = g_w1c; }
    else if constexpr (MODE==2){ W = g_w2t; }
    else if constexpr (MODE==3){ W = g_w3t; }
    else if constexpr (MODE==4){ W = g_w4t; }
    else { W = (n0 < HID) ? g_w1a : g_w1b; }
    const int nW = (MODE==7 && n0 >= HID) ? (n0 - HID) : n0;

    auto load_chunk = [&](int kc, int st){
        const int k0 = kc * BKT;
        fp16* stg = sm + st*STG_T;
        #pragma unroll
        for (int j = 0; j < CPT; j++){
            int p = tid + j*256;
            int r = p >> RSH, c = (p & CMSK) * 8;
            int k = k0 + c;
            const fp16 *pa;
            if constexpr (MODE==1){
                pa = g_ea + (size_t)(m0 + r)*ED + k;
            } else if constexpr (MODE==2){
                pa = g_h + (size_t)(m0 + r)*HID + k;
            } else if constexpr (MODE==3){
                int node = min(m0 + r, NN-1);
                if (k < HID) pa = g_x     + (size_t)node*HID + k;
                else         pa = g_agg_h + (size_t)node*HID + (k - HID);
            } else if constexpr (MODE==4){
                int node = min(m0 + r, NN-1);
                pa = g_u + (size_t)node*HID + k;
            } else {
                int node = min(m0 + r, NN-1);
                pa = g_x + (size_t)node*HID + k;
            }
            cp16(smem_u32(stg + r*BKP_T + c), pa);
        }
        #pragma unroll
        for (int j = 0; j < CPT; j++){
            int p = tid + j*256;
            int r = p >> RSH, c = (p & CMSK) * 8;
            size_t o = (size_t)(nW + r)*KTOT + k0 + c;
            cp16(smem_u32(stg + ASZ_T + r*BKP_T + c), W + o);
        }
        CP_COMMIT();
    };

    // prologue: stages 0 and 1
    load_chunk(0, 0);
    if (NCK > 1) load_chunk(1, 1);

    for (int kc = 0; kc < NCK; ++kc){
        if (kc + 1 < NCK) CP_WAIT1();
        else              CP_WAIT0();
        __syncthreads();
        if (kc + 2 < NCK) load_chunk(kc + 2, (kc + 2) % NSTAGE);

        fp16* stg = sm + (kc % NSTAGE)*STG_T;
        fp16* sA  = stg;
        fp16* sB  = stg + ASZ_T;

        #pragma unroll
        for (int ks = 0; ks < BKT/16; ++ks){
            const int kk = ks * 16;
            unsigned af[2][4];
            #pragma unroll
            for (int mt = 0; mt < 2; ++mt){
                int row = wm*32 + mt*16 + (lane & 7) + ((lane >> 3) & 1) * 8;
                int col = kk + (lane >> 4) * 8;
                ldsm_x4(af[mt][0], af[mt][1], af[mt][2], af[mt][3],
                        smem_u32(sA + row*BKP_T + col));
            }
            unsigned bf[8][2];
            #pragma unroll
            for (int np = 0; np < 4; ++np){
                int ntl = 2*np + (lane >> 4);
                int row = wn*64 + ntl*8 + (lane & 7);
                int col = kk + ((lane >> 3) & 1) * 8;
                unsigned r0, r1, r2, r3;
                ldsm_x4(r0, r1, r2, r3, smem_u32(sB + row*BKP_T + col));
                bf[2*np][0]=r0; bf[2*np][1]=r1; bf[2*np+1][0]=r2; bf[2*np+1][1]=r3;
            }
            #pragma unroll
            for (int mt = 0; mt < 2; ++mt)
                #pragma unroll
                for (int nt = 0; nt < 8; ++nt)
                    mma_f16(acc[mt][nt], af[mt][0], af[mt][1], af[mt][2], af[mt][3],
                            bf[nt][0], bf[nt][1]);
        }
    }

    // ---- epilogue (scale by WINV) ----
    #pragma unroll
    for (int mt = 0; mt < 2; ++mt){
        const int rl0 = wm*32 + mt*16 + g;
        const int rl1 = rl0 + 8;
        int s0 = 0, s1 = 0, d0 = 0, d1 = 0;
        if constexpr (MODE==1){ s0 = sSrc[rl0]; s1 = sSrc[rl1]; d0 = sDst[rl0]; d1 = sDst[rl1]; }
        if constexpr (MODE==2){ d0 = sDst[rl0]; d1 = sDst[rl1]; }
        #pragma unroll
        for (int nt = 0; nt < 8; ++nt){
            const int col = n0 + wn*64 + nt*8 + t*2;
            float bv0 = 0.f, bv1 = 0.f;
            if constexpr (HAS_BIAS){ bv0 = bias[col]; bv1 = bias[col+1]; }
            float v00 = acc[mt][nt][0]*WINV + bv0;
            float v01 = acc[mt][nt][1]*WINV + bv1;
            float v10 = acc[mt][nt][2]*WINV + bv0;
            float v11 = acc[mt][nt][3]*WINV + bv1;
            if constexpr (MODE==1){
                __half2 p0 = *(const __half2*)&g_P[(size_t)s0*HID + col];
                __half2 q0 = *(const __half2*)&g_Q[(size_t)d0*HID + col];
                __half2 p1 = *(const __half2*)&g_P[(size_t)s1*HID + col];
                __half2 q1 = *(const __half2*)&g_Q[(size_t)d1*HID + col];
                v00 = mishf(v00 + __half2float(p0.x) + __half2float(q0.x));
                v01 = mishf(v01 + __half2float(p0.y) + __half2float(q0.y));
                v10 = mishf(v10 + __half2float(p1.x) + __half2float(q1.x));
                v11 = mishf(v11 + __half2float(p1.y) + __half2float(q1.y));
                size_t o0 = (size_t)(m0+rl0)*HID + col;
                size_t o1 = (size_t)(m0+rl1)*HID + col;
                *(uint32_t*)&g_h[o0] = pack2h(__float2half(v00), __float2half(v01));
                *(uint32_t*)&g_h[o1] = pack2h(__float2half(v10), __float2half(v11));
            } else if constexpr (MODE==2){
                v00 = mishf(v00); v01 = mishf(v01); v10 = mishf(v10); v11 = mishf(v11);
                float p00 = __shfl_xor_sync(0xffffffffu, v00, 1);
                float p01 = __shfl_xor_sync(0xffffffffu, v01, 1);
                float p10 = __shfl_xor_sync(0xffffffffu, v10, 1);
                float p11 = __shfl_xor_sync(0xffffffffu, v11, 1);
                if ((t & 1) == 0){
                    atomicAdd((float4*)&g_agg[(size_t)d0*HID + col], make_float4(v00, v01, p00, p01));
                    atomicAdd((float4*)&g_agg[(size_t)d1*HID + col], make_float4(v10, v11, p10, p11));
                }
            } else if constexpr (MODE==3){
                const int r0i = m0 + rl0, r1i = m0 + rl1;
                if (r0i < NN){
                    size_t o = (size_t)r0i*HID + col;
                    *(uint32_t*)&g_u[o] = pack2h(__float2half(mishf(v00)), __float2half(mishf(v01)));
                }
                if (r1i < NN){
                    size_t o = (size_t)r1i*HID + col;
                    *(uint32_t*)&g_u[o] = pack2h(__float2half(mishf(v10)), __float2half(mishf(v11)));
                }
            } else if constexpr (MODE==4){
                const int r0i = m0 + rl0, r1i = m0 + rl1;
                if (r0i < NN){
                    float2 xv = *(const float2*)&xres[(size_t)r0i*HID + col];
                    *(float2*)&g_y[(size_t)r0i*HID + col] = make_float2(v00 + xv.x, v01 + xv.y);
                }
                if (r1i < NN){
                    float2 xv = *(const float2*)&xres[(size_t)r1i*HID + col];
                    *(float2*)&g_y[(size_t)r1i*HID + col] = make_float2(v10 + xv.x, v11 + xv.y);
                }
            } else { // MODE 7: fp16 P/Q
                fp16* dst = (n0 < HID) ? g_P : g_Q;
                const int cw = nW + wn*64 + nt*8 + t*2;
                const int r0i = m0 + rl0, r1i = m0 + rl1;
                if (r0i < NN)
                    *(uint32_t*)&dst[(size_t)r0i*HID + cw] = pack2h(__float2half(v00), __float2half(v01));
                if (r1i < NN)
                    *(uint32_t*)&dst[(size_t)r1i*HID + cw] = pack2h(__float2half(v10), __float2half(v11));
            }
        }
    }
}

// ---------------- LayerNorm ----------------
__global__ __launch_bounds__(128)
void ln_kernel(const float* __restrict__ gamma, const float* __restrict__ beta,
               float* __restrict__ out)
{
    const int row = blockIdx.x, tid = threadIdx.x;
    float4 v = *((const float4*)(g_y + (size_t)row*HID) + tid);
    float s  = v.x + v.y + v.z + v.w;
    float ss = fmaf(v.x, v.x, fmaf(v.y, v.y, fmaf(v.z, v.z, v.w*v.w)));
    #pragma unroll
    for (int o = 16; o > 0; o >>= 1){
        s  += __shfl_xor_sync(0xffffffffu, s,  o);
        ss += __shfl_xor_sync(0xffffffffu, ss, o);
    }
    __shared__ float sh_s[4], sh_ss[4];
    if ((tid & 31) == 0){ sh_s[tid >> 5] = s; sh_ss[tid >> 5] = ss; }
    __syncthreads();
    s  = sh_s[0]  + sh_s[1]  + sh_s[2]  + sh_s[3];
    ss = sh_ss[0] + sh_ss[1] + sh_ss[2] + sh_ss[3];
    const float mu  = s * (1.f / HID);
    const float var = ss * (1.f / HID) - mu * mu;
    const float inv = rsqrtf(var + 1e-5f);
    float4 gm = ((const float4*)gamma)[tid];
    float4 bt = ((const float4*)beta)[tid];
    float4 o;
    o.x = (v.x - mu) * inv * gm.x + bt.x;
    o.y = (v.y - mu) * inv * gm.y + bt.y;
    o.z = (v.z - mu) * inv * gm.z + bt.z;
    o.w = (v.w - mu) * inv * gm.w + bt.w;
    *((float4*)(out + (size_t)row*HID) + tid) = o;
}

// ---------------- launch ----------------
extern "C" void kernel_launch(void* const* d_in, const int* in_sizes, int n_in,
                              void* d_out, int out_size)
{
    (void)in_sizes; (void)n_in; (void)out_size;
    const float* x     = (const float*)d_in[0];
    const void*  ei    = d_in[1];
    const float* ea    = (const float*)d_in[2];
    const float* W1    = (const float*)d_in[3];
    const float* b1    = (const float*)d_in[4];
    const float* W2    = (const float*)d_in[5];
    const float* b2    = (const float*)d_in[6];
    const float* W3    = (const float*)d_in[7];
    const float* b3    = (const float*)d_in[8];
    const float* W4    = (const float*)d_in[9];
    const float* b4    = (const float*)d_in[10];
    const float* gamma = (const float*)d_in[11];
    const float* beta  = (const float*)d_in[12];
    float* out = (float*)d_out;

    cudaFuncSetAttribute((const void*)gemm_kernel<7,64>, cudaFuncAttributeMaxDynamicSharedMemorySize, SMEM_BK64);
    cudaFuncSetAttribute((const void*)gemm_kernel<1,32>, cudaFuncAttributeMaxDynamicSharedMemorySize, SMEM_BK32);
    cudaFuncSetAttribute((const void*)gemm_kernel<2,32>, cudaFuncAttributeMaxDynamicSharedMemorySize, SMEM_BK32);
    cudaFuncSetAttribute((const void*)gemm_kernel<3,64>, cudaFuncAttributeMaxDynamicSharedMemorySize, SMEM_BK64);
    cudaFuncSetAttribute((const void*)gemm_kernel<4,64>, cudaFuncAttributeMaxDynamicSharedMemorySize, SMEM_BK64);

    k_split_all  <<<(SPLIT_ALL_TOT + 255)/256, 256>>>(x, W1, W2, W3, W4);   // 1
    k_split_ea   <<<(NE*ED + 255)/256, 256>>>(ea);                          // 2
    k_decode_zero<<<(NN*HID + 255)/256, 256>>>(ei);                         // 3

    dim3 gPQ(2*HID/BN, (NN + BM - 1)/BM);    // (8, 157)
    dim3 gE(HID/BN, NE/BM);                  // (4, 2500)
    dim3 gN(HID/BN, (NN + BM - 1)/BM);       // (4, 157)
    gemm_kernel<7,64><<<gPQ, 256, SMEM_BK64>>>(nullptr, nullptr);  // 4: P|Q (fp16)
    gemm_kernel<1,32><<<gE, 256, SMEM_BK32>>>(b1, nullptr);        // 5: h
    gemm_kernel<2,32><<<gE, 256, SMEM_BK32>>>(b2, nullptr);        // 6: messages+scatter
    k_split_agg  <<<(NN*HID + 255)/256, 256>>>();                  // 7
    gemm_kernel<3,64><<<gN, 256, SMEM_BK64>>>(b3, nullptr);        // 8: u
    gemm_kernel<4,64><<<gN, 256, SMEM_BK64>>>(b4, x);              // 9: y
    ln_kernel<<<NN, 128>>>(gamma, beta, out);                      // 10
}

// round 17
// speedup vs baseline: 1.4049x; 1.1160x over previous
#include <cuda_runtime.h>
#include <cuda_fp16.h>
#include <math.h>
#include <stdint.h>

using fp16 = __half;

constexpr int NN  = 20000;      // nodes
constexpr int NE  = 320000;     // edges
constexpr int HID = 512;
constexpr int ED  = 64;
constexpr int KC3 = 2*HID;      // 1024

constexpr int BM = 128, BN = 128, PAD = 8;
constexpr int PQW = 136;        // P/Q smem row stride (16B-aligned, conflict-free)

// smem sizes (bytes)
constexpr int SMEM_BK64 = 3*( (BM+BN)*(64+PAD) )*(int)sizeof(fp16);                   // 110592
constexpr int SMEM_M1   = 2*( (BM+BN)*(32+PAD) )*(int)sizeof(fp16) + 2*BM*PQW*2;      // 110592
constexpr int SMEM_M2   = 4*( (BM+BN)*(32+PAD) )*(int)sizeof(fp16);                   // 81920

constexpr float WSC  = 32.0f;           // weight pre-scale (power of 2, exact)
constexpr float WINV = 1.0f/32.0f;

// ---------------- device scratch ----------------
__device__ fp16 g_x[NN*HID];
__device__ fp16 g_ea[NE*ED];
__device__ fp16 g_w1a[HID*HID];
__device__ fp16 g_w1b[HID*HID];
__device__ fp16 g_w1c[HID*ED];
__device__ fp16 g_w2t[HID*HID];
__device__ fp16 g_w3t[HID*KC3];
__device__ fp16 g_w4t[HID*HID];
__device__ int   g_ei[2*NE];
__device__ fp16  g_P[NN*HID];
__device__ fp16  g_Q[NN*HID];
__device__ fp16  g_h[(size_t)NE*HID];
__device__ float g_agg[NN*HID];
__device__ fp16  g_agg_h[NN*HID];
__device__ fp16  g_u[NN*HID];
__device__ float g_y[NN*HID];

// ---------------- helpers ----------------
__device__ __forceinline__ float mishf(float x){
    float t   = __expf(fminf(x, 15.f));
    float num = t * (t + 2.f);
    return x * __fdividef(num, num + 2.f);
}
__device__ __forceinline__ unsigned smem_u32(const void* p){
    return (unsigned)__cvta_generic_to_shared(p);
}
__device__ __forceinline__ void ldsm_x4(unsigned &r0, unsigned &r1, unsigned &r2, unsigned &r3, unsigned addr){
    asm volatile("ldmatrix.sync.aligned.m8n8.x4.shared.b16 {%0,%1,%2,%3}, [%4];"
                 : "=r"(r0), "=r"(r1), "=r"(r2), "=r"(r3) : "r"(addr));
}
__device__ __forceinline__ void mma_f16(float* c, unsigned a0, unsigned a1, unsigned a2, unsigned a3,
                                        unsigned b0, unsigned b1){
    asm volatile("mma.sync.aligned.m16n8k16.row.col.f32.f16.f16.f32 "
                 "{%0,%1,%2,%3}, {%4,%5,%6,%7}, {%8,%9}, {%0,%1,%2,%3};"
                 : "+f"(c[0]), "+f"(c[1]), "+f"(c[2]), "+f"(c[3])
                 : "r"(a0), "r"(a1), "r"(a2), "r"(a3), "r"(b0), "r"(b1));
}
__device__ __forceinline__ uint32_t pack2h(fp16 a, fp16 b){
    __half2 p; p.x = a; p.y = b;
    return *(uint32_t*)&p;
}
__device__ __forceinline__ void cp16(uint32_t dst, const void* src){
    asm volatile("cp.async.cg.shared.global [%0], [%1], 16;" :: "r"(dst), "l"(src));
}
#define CP_COMMIT() asm volatile("cp.async.commit_group;" ::: "memory")
#define CP_WAIT2()  asm volatile("cp.async.wait_group 2;" ::: "memory")
#define CP_WAIT1()  asm volatile("cp.async.wait_group 1;" ::: "memory")
#define CP_WAIT0()  asm volatile("cp.async.wait_group 0;" ::: "memory")

// ---------------- prep kernels (fused) ----------------
constexpr int NX   = NN*HID;
constexpr int NW1A = HID*HID;
constexpr int NW1B = HID*HID;
constexpr int NW1C = ED*HID;
constexpr int NW2  = HID*HID;
constexpr int NW3  = KC3*HID;
constexpr int NW4  = HID*HID;
constexpr int SPLIT_ALL_TOT = NX + NW1A + NW1B + NW1C + NW2 + NW3 + NW4;

__global__ void k_split_all(const float* __restrict__ x,
                            const float* __restrict__ W1,
                            const float* __restrict__ W2,
                            const float* __restrict__ W3,
                            const float* __restrict__ W4){
    int i = blockIdx.x * blockDim.x + threadIdx.x;
    if (i >= SPLIT_ALL_TOT) return;
    if (i < NX){
        g_x[i] = __float2half(x[i]);
        return;
    }
    i -= NX;
    const float* src; fp16 *w; int K;
    if      (i < NW1A){                              src = W1;                     w=g_w1a; K=HID; }
    else if ((i -= NW1A) < NW1B){                    src = W1 + (size_t)HID*HID;   w=g_w1b; K=HID; }
    else if ((i -= NW1B) < NW1C){                    src = W1 + (size_t)2*HID*HID; w=g_w1c; K=ED; }
    else if ((i -= NW1C) < NW2){                     src = W2;                     w=g_w2t; K=HID; }
    else if ((i -= NW2)  < NW3){                     src = W3;                     w=g_w3t; K=KC3; }
    else { i -= NW3;                                 src = W4;                     w=g_w4t; K=HID; }
    int k = i / HID, n = i % HID;
    w[(size_t)n*K + k] = __float2half(src[i] * WSC);
}
__global__ void k_split_ea(const float* __restrict__ s){
    int i = blockIdx.x * blockDim.x + threadIdx.x;
    if (i < NE*ED) g_ea[i] = __float2half(s[i]);
}
// decode edge_index (int64 vs int32 defensive) + zero agg
__global__ void k_decode_zero(const void* __restrict__ ei_raw){
    int i = blockIdx.x * blockDim.x + threadIdx.x;
    if (i < 2*NE){
        const long long* p64 = (const long long*)ei_raw;
        bool is64 = true;
        #pragma unroll
        for (int j = 0; j < 4; j++){
            long long v = p64[j];
            if (v < 0 || v >= NN) is64 = false;
        }
        g_ei[i] = is64 ? (int)p64[i] : ((const int*)ei_raw)[i];
    }
    if (i < NN*HID) g_agg[i] = 0.f;
}
__global__ void k_split_agg(){
    int i = blockIdx.x * blockDim.x + threadIdx.x;
    if (i < NN*HID) g_agg_h[i] = __float2half(g_agg[i]);
}

// ---------------- fp16 GEMM, BN=128, per-mode BK/NSTAGE, cp.async ----------------
// MODE 7: [P|Q] = x @ [W1a|W1b]                   (BK=64, NST=3)
// MODE 1: h = mish(ea@W1c + P[src]+Q[dst]+b1)     (BK=32, NST=2, smem PQ prefetch)
// MODE 2: msg = mish(h @ W2 + b2); RED scatter    (BK=32, NST=4)
// MODE 3: u = mish([x|agg_h] @ W3 + b3)           (BK=64, NST=3)
// MODE 4: y = x + u @ W4 + b4                     (BK=64, NST=3)
template<int MODE, int BKT, int NST>
__global__ __launch_bounds__(256, 2)
void gemm_kernel(const float* __restrict__ bias, const float* __restrict__ xres)
{
    constexpr int KTOT  = (MODE==1) ? ED : (MODE==3) ? KC3 : HID;
    constexpr int NCK   = KTOT / BKT;
    constexpr int BKP_T = BKT + PAD;
    constexpr int ASZ_T = BM*BKP_T;
    constexpr int BSZ_T = BN*BKP_T;
    constexpr int STG_T = ASZ_T + BSZ_T;
    constexpr int CPT   = BKT/16;          // 16B chunks per thread per tile
    constexpr int RSH   = (BKT==64) ? 3 : 2;
    constexpr int CMSK  = (BKT==64) ? 7 : 3;
    constexpr bool HAS_BIAS = (MODE != 7);

    extern __shared__ __align__(16) char smem_raw[];
    fp16* sm = (fp16*)smem_raw;
    __shared__ int sSrc[BM];
    __shared__ int sDst[BM];

    const int tid = threadIdx.x;
    const int n0  = blockIdx.x * BN;
    const int m0  = blockIdx.y * BM;

    fp16* sP = sm + NST*STG_T;          // MODE1 only
    fp16* sQ = sP + BM*PQW;

    if constexpr (MODE==1 || MODE==2){
        if (tid < BM){
            if (MODE == 1) sSrc[tid] = g_ei[m0 + tid];
            sDst[tid] = g_ei[NE + m0 + tid];
        }
    }
    if constexpr (MODE==1) __syncthreads();   // PQ prefetch reads sSrc/sDst

    const int wid = tid >> 5, lane = tid & 31;
    const int wm  = wid >> 1, wn = wid & 1;   // 4x2 warp grid, warp tile 32x64
    const int g   = lane >> 2, t = lane & 3;

    float acc[2][8][4];
    #pragma unroll
    for (int a = 0; a < 2; a++)
        #pragma unroll
        for (int b = 0; b < 8; b++)
            #pragma unroll
            for (int c = 0; c < 4; c++) acc[a][b][c] = 0.f;

    const fp16 *W;
    if      constexpr (MODE==1){ W = g_w1c; }
    else if constexpr (MODE==2){ W = g_w2t; }
    else if constexpr (MODE==3){ W = g_w3t; }
    else if constexpr (MODE==4){ W = g_w4t; }
    else { W = (n0 < HID) ? g_w1a : g_w1b; }
    const int nW = (MODE==7 && n0 >= HID) ? (n0 - HID) : n0;

    auto load_chunk = [&](int kc, int st){
        const int k0 = kc * BKT;
        fp16* stg = sm + st*STG_T;
        #pragma unroll
        for (int j = 0; j < CPT; j++){
            int p = tid + j*256;
            int r = p >> RSH, c = (p & CMSK) * 8;
            int k = k0 + c;
            const fp16 *pa;
            if constexpr (MODE==1){
                pa = g_ea + (size_t)(m0 + r)*ED + k;
            } else if constexpr (MODE==2){
                pa = g_h + (size_t)(m0 + r)*HID + k;
            } else if constexpr (MODE==3){
                int node = min(m0 + r, NN-1);
                if (k < HID) pa = g_x     + (size_t)node*HID + k;
                else         pa = g_agg_h + (size_t)node*HID + (k - HID);
            } else if constexpr (MODE==4){
                int node = min(m0 + r, NN-1);
                pa = g_u + (size_t)node*HID + k;
            } else {
                int node = min(m0 + r, NN-1);
                pa = g_x + (size_t)node*HID + k;
            }
            cp16(smem_u32(stg + r*BKP_T + c), pa);
        }
        #pragma unroll
        for (int j = 0; j < CPT; j++){
            int p = tid + j*256;
            int r = p >> RSH, c = (p & CMSK) * 8;
            size_t o = (size_t)(nW + r)*KTOT + k0 + c;
            cp16(smem_u32(stg + ASZ_T + r*BKP_T + c), W + o);
        }
        CP_COMMIT();
    };

    // ---- prologue ----
    if constexpr (MODE == 1){
        load_chunk(0, 0);
        load_chunk(1, 1);
        // PQ prefetch (group 3): 128 rows x 128 fp16 each
        #pragma unroll
        for (int j = 0; j < 8; j++){
            int p = tid + j*256;
            int r = p >> 4, ch = (p & 15) * 8;
            cp16(smem_u32(sP + r*PQW + ch), g_P + (size_t)sSrc[r]*HID + n0 + ch);
        }
        #pragma unroll
        for (int j = 0; j < 8; j++){
            int p = tid + j*256;
            int r = p >> 4, ch = (p & 15) * 8;
            cp16(smem_u32(sQ + r*PQW + ch), g_Q + (size_t)sDst[r]*HID + n0 + ch);
        }
        CP_COMMIT();
    } else {
        load_chunk(0, 0);
        if (NCK > 1) load_chunk(1, 1);
        if constexpr (NST == 4){ if (NCK > 2) load_chunk(2, 2); }
    }

    for (int kc = 0; kc < NCK; ++kc){
        if constexpr (MODE == 1){
            if (kc == 0) CP_WAIT2(); else CP_WAIT1();
        } else if constexpr (NST == 4){
            if (kc + 2 < NCK) CP_WAIT2(); else if (kc + 1 < NCK) CP_WAIT1(); else CP_WAIT0();
        } else {
            if (kc + 1 < NCK) CP_WAIT1(); else CP_WAIT0();
        }
        __syncthreads();
        if constexpr (MODE != 1){
            if (kc + NST - 1 < NCK) load_chunk(kc + NST - 1, (kc + NST - 1) % NST);
        }

        fp16* stg = sm + (kc % NST)*STG_T;
        fp16* sA  = stg;
        fp16* sB  = stg + ASZ_T;

        #pragma unroll
        for (int ks = 0; ks < BKT/16; ++ks){
            const int kk = ks * 16;
            unsigned af[2][4];
            #pragma unroll
            for (int mt = 0; mt < 2; ++mt){
                int row = wm*32 + mt*16 + (lane & 7) + ((lane >> 3) & 1) * 8;
                int col = kk + (lane >> 4) * 8;
                ldsm_x4(af[mt][0], af[mt][1], af[mt][2], af[mt][3],
                        smem_u32(sA + row*BKP_T + col));
            }
            unsigned bf[8][2];
            #pragma unroll
            for (int np = 0; np < 4; ++np){
                int ntl = 2*np + (lane >> 4);
                int row = wn*64 + ntl*8 + (lane & 7);
                int col = kk + ((lane >> 3) & 1) * 8;
                unsigned r0, r1, r2, r3;
                ldsm_x4(r0, r1, r2, r3, smem_u32(sB + row*BKP_T + col));
                bf[2*np][0]=r0; bf[2*np][1]=r1; bf[2*np+1][0]=r2; bf[2*np+1][1]=r3;
            }
            #pragma unroll
            for (int mt = 0; mt < 2; ++mt)
                #pragma unroll
                for (int nt = 0; nt < 8; ++nt)
                    mma_f16(acc[mt][nt], af[mt][0], af[mt][1], af[mt][2], af[mt][3],
                            bf[nt][0], bf[nt][1]);
        }
    }

    if constexpr (MODE == 1){ CP_WAIT0(); __syncthreads(); }   // PQ tiles ready

    // ---- epilogue (scale by WINV) ----
    #pragma unroll
    for (int mt = 0; mt < 2; ++mt){
        const int rl0 = wm*32 + mt*16 + g;
        const int rl1 = rl0 + 8;
        int d0 = 0, d1 = 0;
        if constexpr (MODE==2){ d0 = sDst[rl0]; d1 = sDst[rl1]; }
        #pragma unroll
        for (int nt = 0; nt < 8; ++nt){
            const int col = n0 + wn*64 + nt*8 + t*2;
            float bv0 = 0.f, bv1 = 0.f;
            if constexpr (HAS_BIAS){ bv0 = bias[col]; bv1 = bias[col+1]; }
            float v00 = acc[mt][nt][0]*WINV + bv0;
            float v01 = acc[mt][nt][1]*WINV + bv1;
            float v10 = acc[mt][nt][2]*WINV + bv0;
            float v11 = acc[mt][nt][3]*WINV + bv1;
            if constexpr (MODE==1){
                const int lc = wn*64 + nt*8 + t*2;
                __half2 p0 = *(const __half2*)&sP[rl0*PQW + lc];
                __half2 q0 = *(const __half2*)&sQ[rl0*PQW + lc];
                __half2 p1 = *(const __half2*)&sP[rl1*PQW + lc];
                __half2 q1 = *(const __half2*)&sQ[rl1*PQW + lc];
                v00 = mishf(v00 + __half2float(p0.x) + __half2float(q0.x));
                v01 = mishf(v01 + __half2float(p0.y) + __half2float(q0.y));
                v10 = mishf(v10 + __half2float(p1.x) + __half2float(q1.x));
                v11 = mishf(v11 + __half2float(p1.y) + __half2float(q1.y));
                size_t o0 = (size_t)(m0+rl0)*HID + col;
                size_t o1 = (size_t)(m0+rl1)*HID + col;
                *(uint32_t*)&g_h[o0] = pack2h(__float2half(v00), __float2half(v01));
                *(uint32_t*)&g_h[o1] = pack2h(__float2half(v10), __float2half(v11));
            } else if constexpr (MODE==2){
                v00 = mishf(v00); v01 = mishf(v01); v10 = mishf(v10); v11 = mishf(v11);
                float p00 = __shfl_xor_sync(0xffffffffu, v00, 1);
                float p01 = __shfl_xor_sync(0xffffffffu, v01, 1);
                float p10 = __shfl_xor_sync(0xffffffffu, v10, 1);
                float p11 = __shfl_xor_sync(0xffffffffu, v11, 1);
                if ((t & 1) == 0){
                    atomicAdd((float4*)&g_agg[(size_t)d0*HID + col], make_float4(v00, v01, p00, p01));
                    atomicAdd((float4*)&g_agg[(size_t)d1*HID + col], make_float4(v10, v11, p10, p11));
                }
            } else if constexpr (MODE==3){
                const int r0i = m0 + rl0, r1i = m0 + rl1;
                if (r0i < NN){
                    size_t o = (size_t)r0i*HID + col;
                    *(uint32_t*)&g_u[o] = pack2h(__float2half(mishf(v00)), __float2half(mishf(v01)));
                }
                if (r1i < NN){
                    size_t o = (size_t)r1i*HID + col;
                    *(uint32_t*)&g_u[o] = pack2h(__float2half(mishf(v10)), __float2half(mishf(v11)));
                }
            } else if constexpr (MODE==4){
                const int r0i = m0 + rl0, r1i = m0 + rl1;
                if (r0i < NN){
                    float2 xv = *(const float2*)&xres[(size_t)r0i*HID + col];
                    *(float2*)&g_y[(size_t)r0i*HID + col] = make_float2(v00 + xv.x, v01 + xv.y);
                }
                if (r1i < NN){
                    float2 xv = *(const float2*)&xres[(size_t)r1i*HID + col];
                    *(float2*)&g_y[(size_t)r1i*HID + col] = make_float2(v10 + xv.x, v11 + xv.y);
                }
            } else { // MODE 7: fp16 P/Q
                fp16* dst = (n0 < HID) ? g_P : g_Q;
                const int cw = nW + wn*64 + nt*8 + t*2;
                const int r0i = m0 + rl0, r1i = m0 + rl1;
                if (r0i < NN)
                    *(uint32_t*)&dst[(size_t)r0i*HID + cw] = pack2h(__float2half(v00), __float2half(v01));
                if (r1i < NN)
                    *(uint32_t*)&dst[(size_t)r1i*HID + cw] = pack2h(__float2half(v10), __float2half(v11));
            }
        }
    }
}

// ---------------- LayerNorm ----------------
__global__ __launch_bounds__(128)
void ln_kernel(const float* __restrict__ gamma, const float* __restrict__ beta,
               float* __restrict__ out)
{
    const int row = blockIdx.x, tid = threadIdx.x;
    float4 v = *((const float4*)(g_y + (size_t)row*HID) + tid);
    float s  = v.x + v.y + v.z + v.w;
    float ss = fmaf(v.x, v.x, fmaf(v.y, v.y, fmaf(v.z, v.z, v.w*v.w)));
    #pragma unroll
    for (int o = 16; o > 0; o >>= 1){
        s  += __shfl_xor_sync(0xffffffffu, s,  o);
        ss += __shfl_xor_sync(0xffffffffu, ss, o);
    }
    __shared__ float sh_s[4], sh_ss[4];
    if ((tid & 31) == 0){ sh_s[tid >> 5] = s; sh_ss[tid >> 5] = ss; }
    __syncthreads();
    s  = sh_s[0]  + sh_s[1]  + sh_s[2]  + sh_s[3];
    ss = sh_ss[0] + sh_ss[1] + sh_ss[2] + sh_ss[3];
    const float mu  = s * (1.f / HID);
    const float var = ss * (1.f / HID) - mu * mu;
    const float inv = rsqrtf(var + 1e-5f);
    float4 gm = ((const float4*)gamma)[tid];
    float4 bt = ((const float4*)beta)[tid];
    float4 o;
    o.x = (v.x - mu) * inv * gm.x + bt.x;
    o.y = (v.y - mu) * inv * gm.y + bt.y;
    o.z = (v.z - mu) * inv * gm.z + bt.z;
    o.w = (v.w - mu) * inv * gm.w + bt.w;
    *((float4*)(out + (size_t)row*HID) + tid) = o;
}

// ---------------- launch ----------------
extern "C" void kernel_launch(void* const* d_in, const int* in_sizes, int n_in,
                              void* d_out, int out_size)
{
    (void)in_sizes; (void)n_in; (void)out_size;
    const float* x     = (const float*)d_in[0];
    const void*  ei    = d_in[1];
    const float* ea    = (const float*)d_in[2];
    const float* W1    = (const float*)d_in[3];
    const float* b1    = (const float*)d_in[4];
    const float* W2    = (const float*)d_in[5];
    const float* b2    = (const float*)d_in[6];
    const float* W3    = (const float*)d_in[7];
    const float* b3    = (const float*)d_in[8];
    const float* W4    = (const float*)d_in[9];
    const float* b4    = (const float*)d_in[10];
    const float* gamma = (const float*)d_in[11];
    const float* beta  = (const float*)d_in[12];
    float* out = (float*)d_out;

    cudaFuncSetAttribute((const void*)gemm_kernel<7,64,3>, cudaFuncAttributeMaxDynamicSharedMemorySize, SMEM_BK64);
    cudaFuncSetAttribute((const void*)gemm_kernel<1,32,2>, cudaFuncAttributeMaxDynamicSharedMemorySize, SMEM_M1);
    cudaFuncSetAttribute((const void*)gemm_kernel<2,32,4>, cudaFuncAttributeMaxDynamicSharedMemorySize, SMEM_M2);
    cudaFuncSetAttribute((const void*)gemm_kernel<3,64,3>, cudaFuncAttributeMaxDynamicSharedMemorySize, SMEM_BK64);
    cudaFuncSetAttribute((const void*)gemm_kernel<4,64,3>, cudaFuncAttributeMaxDynamicSharedMemorySize, SMEM_BK64);

    k_split_all  <<<(SPLIT_ALL_TOT + 255)/256, 256>>>(x, W1, W2, W3, W4);   // 1
    k_split_ea   <<<(NE*ED + 255)/256, 256>>>(ea);                          // 2
    k_decode_zero<<<(NN*HID + 255)/256, 256>>>(ei);                         // 3

    dim3 gPQ(2*HID/BN, (NN + BM - 1)/BM);    // (8, 157)
    dim3 gE(HID/BN, NE/BM);                  // (4, 2500)
    dim3 gN(HID/BN, (NN + BM - 1)/BM);       // (4, 157)
    gemm_kernel<7,64,3><<<gPQ, 256, SMEM_BK64>>>(nullptr, nullptr);  // 4: P|Q (fp16)
    gemm_kernel<1,32,2><<<gE, 256, SMEM_M1>>>(b1, nullptr);          // 5: h (PQ prefetch)
    gemm_kernel<2,32,4><<<gE, 256, SMEM_M2>>>(b2, nullptr);          // 6: messages+scatter
    k_split_agg  <<<(NN*HID + 255)/256, 256>>>();                    // 7
    gemm_kernel<3,64,3><<<gN, 256, SMEM_BK64>>>(b3, nullptr);        // 8: u
    gemm_kernel<4,64,3><<<gN, 256, SMEM_BK64>>>(b4, x);              // 9: y
    ln_kernel<<<NN, 128>>>(gamma, beta, out);                        // 10
}